// round 6
// baseline (speedup 1.0000x reference)
#include <cuda_runtime.h>

// ---------------- problem constants ----------------
#define Bn    2
#define Sn    1024
#define Hn    8
#define DIMn  128
#define LCMP  32
#define NCMP  63          // (1024-32)/16+1
#define NSLC  61          // (1024-64)/16+1
#define BQ    64
#define NQB   (Sn / BQ)   // 16
#define WINR  128
#define QSTR  129         // padded row stride (conflict-free scalar LDS)
#define PSTR  341         // logit buffer row stride (>=320, odd-ish vs 32 banks)
#define NEG_INF (-1e30f)

#define SCALE_MUL 0.08838834764831845f   // 1/sqrt(128): slc & window
#define SQRT_D    11.313708498984761f    // sqrt(128): cmp branch (reference divides by scale)

// scratch for compressed K/V: [b][h][n][d]
__device__ float g_cmpK[Bn * Hn * NCMP * DIMn];
__device__ float g_cmpV[Bn * Hn * NCMP * DIMn];

// ---------------- kernel A: compressed K/V ----------------
__global__ void __launch_bounds__(256) cmp_kv_kernel(
    const float* __restrict__ k, const float* __restrict__ v,
    const float* __restrict__ wck, const float* __restrict__ bck,
    const float* __restrict__ wcv, const float* __restrict__ bcv)
{
    __shared__ float swk[LCMP], swv[LCMP], sb[2];
    int tid = threadIdx.x;
    if (tid < LCMP) { swk[tid] = wck[tid]; swv[tid] = wcv[tid]; }
    if (tid == 0)   { sb[0] = bck[0]; sb[1] = bcv[0]; }
    __syncthreads();

    int idx = blockIdx.x * 256 + tid;
    if (idx >= Bn * Hn * NCMP * DIMn) return;
    int d  = idx & (DIMn - 1);
    int n  = (idx >> 7) % NCMP;
    int bh = idx / (NCMP * DIMn);
    int h  = bh & (Hn - 1);
    int b  = bh >> 3;

    const float* kb = k + ((size_t)(b * Sn + n * 16) * Hn + h) * DIMn + d;
    const float* vb = v + ((size_t)(b * Sn + n * 16) * Hn + h) * DIMn + d;
    float ak = 0.f, av = 0.f;
#pragma unroll
    for (int l = 0; l < LCMP; ++l) {
        ak += kb[(size_t)l * Hn * DIMn] * swk[l];
        av += vb[(size_t)l * Hn * DIMn] * swv[l];
    }
    g_cmpK[idx] = ak + sb[0];
    g_cmpV[idx] = av + sb[1];
}

// ---------------- helpers for the fused kernel ----------------

// QK GEMM: S[64 x 64-tile] = Qs(64x128) * Ks(64x128)^T, store (scaled+masked) to Pb
// MODE 0 = cmp (mask c>=NCMP), 1 = slc (no mask), 2 = window (range+band mask)
template <int MODE>
__device__ __forceinline__ void gemm_qk(const float* __restrict__ Qs,
                                        const float* __restrict__ Ks,
                                        float* __restrict__ Pb,
                                        int rho, int gg, int cb, float scl, int q0)
{
    float s[4][4];
#pragma unroll
    for (int i = 0; i < 4; ++i)
#pragma unroll
        for (int j = 0; j < 4; ++j) s[i][j] = 0.f;

    const float* qp = Qs + rho * QSTR;
    const float* kp = Ks + gg  * QSTR;
#pragma unroll 4
    for (int kd = 0; kd < DIMn; ++kd) {
        float a0 = qp[kd];
        float a1 = qp[16 * QSTR + kd];
        float a2 = qp[32 * QSTR + kd];
        float a3 = qp[48 * QSTR + kd];
        float b0 = kp[kd];
        float b1 = kp[16 * QSTR + kd];
        float b2 = kp[32 * QSTR + kd];
        float b3 = kp[48 * QSTR + kd];
        s[0][0] += a0 * b0; s[0][1] += a0 * b1; s[0][2] += a0 * b2; s[0][3] += a0 * b3;
        s[1][0] += a1 * b0; s[1][1] += a1 * b1; s[1][2] += a1 * b2; s[1][3] += a1 * b3;
        s[2][0] += a2 * b0; s[2][1] += a2 * b1; s[2][2] += a2 * b2; s[2][3] += a2 * b3;
        s[3][0] += a3 * b0; s[3][1] += a3 * b1; s[3][2] += a3 * b2; s[3][3] += a3 * b3;
    }
#pragma unroll
    for (int i = 0; i < 4; ++i) {
        int r = rho + 16 * i;
#pragma unroll
        for (int j = 0; j < 4; ++j) {
            int c = gg + 16 * j;
            float val = s[i][j] * scl;
            if (MODE == 0) {
                if (c >= NCMP) val = NEG_INF;
            }
            if (MODE == 2) {
                int cgl = cb + c;
                int key = q0 - WINR + cgl;
                bool ok = (key >= 0) && (key < Sn) && (cgl >= r) && (cgl <= r + 2 * WINR);
                if (!ok) val = NEG_INF;
            }
            Pb[r * PSTR + cb + c] = val;
        }
    }
}

// PV GEMM: acc[4][8] += P(64 x 64-tile) * Vs(64x128)
__device__ __forceinline__ void gemm_pv(const float* __restrict__ Pb,
                                        const float* __restrict__ Vs,
                                        float acc[4][8], int rho, int gg, int cb)
{
    const float* pp = Pb + rho * PSTR + cb;
#pragma unroll 2
    for (int cl = 0; cl < 64; ++cl) {
        float p0 = pp[cl];
        float p1 = pp[16 * PSTR + cl];
        float p2 = pp[32 * PSTR + cl];
        float p3 = pp[48 * PSTR + cl];
        const float* vr = Vs + cl * QSTR + gg;
#pragma unroll
        for (int j = 0; j < 8; ++j) {
            float vv = vr[16 * j];
            acc[0][j] += p0 * vv;
            acc[1][j] += p1 * vv;
            acc[2][j] += p2 * vv;
            acc[3][j] += p3 * vv;
        }
    }
}

// two-pass row softmax over Pb[:, 0:NK]; leaves exp() in Pb, 1/rowsum in rinv
__device__ __forceinline__ void softmax_rows(float* __restrict__ Pb,
                                             float* __restrict__ rmax,
                                             float* __restrict__ rinv,
                                             float* __restrict__ red,
                                             int NK, int tid)
{
    int r = tid & 63, part = tid >> 6;
    float m = NEG_INF;
    for (int c = part; c < NK; c += 4) m = fmaxf(m, Pb[r * PSTR + c]);
    red[part * 64 + r] = m;
    __syncthreads();
    if (tid < 64)
        rmax[tid] = fmaxf(fmaxf(red[tid], red[64 + tid]),
                          fmaxf(red[128 + tid], red[192 + tid]));
    __syncthreads();
    float mr = rmax[r];
    float sum = 0.f;
    for (int c = part; c < NK; c += 4) {
        float e = __expf(Pb[r * PSTR + c] - mr);
        Pb[r * PSTR + c] = e;
        sum += e;
    }
    red[part * 64 + r] = sum;
    __syncthreads();
    if (tid < 64)
        rinv[tid] = 1.0f / (red[tid] + red[64 + tid] + red[128 + tid] + red[192 + tid]);
    __syncthreads();
}

// P[r][c] *= gate[r][gi] / rowsum[r]
__device__ __forceinline__ void scale_rows(float* __restrict__ Pb,
                                           const float* __restrict__ rinv,
                                           const float* __restrict__ gts,
                                           int gi, int NK, int tid)
{
    int r = tid & 63, part = tid >> 6;
    float f = gts[r * 3 + gi] * rinv[r];
    for (int c = part; c < NK; c += 4) Pb[r * PSTR + c] *= f;
    __syncthreads();
}

// load a 64x128 tile from q/k/v-layout global memory into padded smem, zero-fill invalid
__device__ __forceinline__ void load_tile_kv(float* __restrict__ dst,
                                             const float* __restrict__ src,
                                             int b, int h, int s_base, int tid, bool check)
{
    for (int idx = tid; idx < 64 * 32; idx += 256) {
        int t = idx >> 5, d4 = idx & 31;
        int srow = s_base + t;
        float4 val = make_float4(0.f, 0.f, 0.f, 0.f);
        if (!check || ((unsigned)srow < (unsigned)Sn))
            val = ((const float4*)(src + ((size_t)(b * Sn + srow) * Hn + h) * DIMn))[d4];
        float* ds = &dst[t * QSTR + (d4 << 2)];
        ds[0] = val.x; ds[1] = val.y; ds[2] = val.z; ds[3] = val.w;
    }
}

// load compressed K/V tile (63 rows), zero row 63
__device__ __forceinline__ void load_tile_cmp(float* __restrict__ dst,
                                              const float* __restrict__ src,
                                              int bh, int tid)
{
    for (int idx = tid; idx < 64 * 32; idx += 256) {
        int t = idx >> 5, d4 = idx & 31;
        float4 val = make_float4(0.f, 0.f, 0.f, 0.f);
        if (t < NCMP)
            val = ((const float4*)(src + ((size_t)bh * NCMP + t) * DIMn))[d4];
        float* ds = &dst[t * QSTR + (d4 << 2)];
        ds[0] = val.x; ds[1] = val.y; ds[2] = val.z; ds[3] = val.w;
    }
}

// ---------------- fused main kernel ----------------
__global__ void __launch_bounds__(256, 1) nsa_main(
    const float* __restrict__ q, const float* __restrict__ k, const float* __restrict__ v,
    const float* __restrict__ wgate, const float* __restrict__ bgate,
    float* __restrict__ out)
{
    extern __shared__ float sm[];
    float* Qs   = sm;                    // 64*129
    float* Ks   = Qs  + 64 * QSTR;       // 64*129
    float* Vs   = Ks  + 64 * QSTR;       // 64*129
    float* Pb   = Vs  + 64 * QSTR;       // 64*341
    float* rinv = Pb  + 64 * PSTR;       // 64
    float* rmax = rinv + 64;             // 64
    float* red  = rmax + 64;             // 256
    float* gts  = red  + 256;            // 192
    float* Cs   = gts  + 192;            // 64
    float* Gb   = Cs   + 64;             // 64
    float* wgs  = Gb   + 64;             // 384
    int*   topi = (int*)(wgs + 384);     // 2

    const int tid = threadIdx.x;
    const int bhq = blockIdx.x;
    const int qb  = bhq & (NQB - 1);
    const int bh  = bhq >> 4;
    const int h   = bh & (Hn - 1);
    const int b   = bh >> 3;
    const int q0  = qb * BQ;
    const int rho = tid >> 4;   // 0..15 row group
    const int gg  = tid & 15;   // 0..15 col group

    // ---- load Q tile + gate weights ----
    {
        const float4* q4 = (const float4*)(q + ((size_t)(b * Sn + q0) * Hn + h) * DIMn);
        for (int idx = tid; idx < 64 * 32; idx += 256) {
            int t = idx >> 5, d4 = idx & 31;
            float4 val = q4[(size_t)t * (Hn * DIMn / 4) + d4];
            float* ds = &Qs[t * QSTR + (d4 << 2)];
            ds[0] = val.x; ds[1] = val.y; ds[2] = val.z; ds[3] = val.w;
        }
        for (int i = tid; i < 3 * DIMn; i += 256) wgs[i] = wgate[i];
    }
    __syncthreads();

    // ---- gates: sigmoid(q . w_gate[c] + b_gate[c]) ----
    if (tid < 192) {
        int r = tid / 3, c = tid - 3 * r;
        float a = bgate[c];
        const float* qr = &Qs[r * QSTR];
        const float* wr = &wgs[c * DIMn];
#pragma unroll 8
        for (int d = 0; d < DIMn; ++d) a += qr[d] * wr[d];
        gts[r * 3 + c] = 1.0f / (1.0f + __expf(-a));
    }
    __syncthreads();

    float acc[4][8];
#pragma unroll
    for (int i = 0; i < 4; ++i)
#pragma unroll
        for (int j = 0; j < 8; ++j) acc[i][j] = 0.f;

    // ================= CMP branch =================
    load_tile_cmp(Ks, g_cmpK, bh, tid);
    load_tile_cmp(Vs, g_cmpV, bh, tid);
    __syncthreads();
    gemm_qk<0>(Qs, Ks, Pb, rho, gg, 0, SQRT_D, q0);
    __syncthreads();
    softmax_rows(Pb, rmax, rinv, red, 64, tid);

    // column sums of normalized P_cmp
    if (tid < NCMP) {
        float s = 0.f;
#pragma unroll 4
        for (int r = 0; r < 64; ++r) s += Pb[r * PSTR + tid] * rinv[r];
        Cs[tid] = s;
    }
    __syncthreads();
    // slc-map convolution: weights 1,2,2,2,1 at i = 4j, 4j-1, 4j-2, 4j-3, 4j-4
    if (tid < NSLC) {
        int j4 = 4 * tid;
        float g = 0.f;
        if (j4 < NCMP)                       g += Cs[j4];
        if (j4 - 1 >= 0 && j4 - 1 < NCMP)    g += 2.f * Cs[j4 - 1];
        if (j4 - 2 >= 0 && j4 - 2 < NCMP)    g += 2.f * Cs[j4 - 2];
        if (j4 - 3 >= 0 && j4 - 3 < NCMP)    g += 2.f * Cs[j4 - 3];
        if (j4 - 4 >= 0 && j4 - 4 < NCMP)    g += Cs[j4 - 4];
        Gb[tid] = g;
    }
    __syncthreads();
    // deterministic top-2 (jax tie rule: lower index first)
    if (tid == 0) {
        int i0 = 0; float v0 = Gb[0];
        for (int j = 1; j < NSLC; ++j) if (Gb[j] > v0) { v0 = Gb[j]; i0 = j; }
        int i1 = 0; float v1 = NEG_INF;
        for (int j = 0; j < NSLC; ++j) if (j != i0 && Gb[j] > v1) { v1 = Gb[j]; i1 = j; }
        topi[0] = i0; topi[1] = i1;
    }
    scale_rows(Pb, rinv, gts, 0, 64, tid);   // fold in gate0 (also syncs -> topi visible)
    gemm_pv(Pb, Vs, acc, rho, gg, 0);
    __syncthreads();

    // ================= SLC branch =================
    {
        int j0 = topi[0], j1 = topi[1];
        load_tile_kv(Ks, k, b, h, j0 * 16, tid, false);
        __syncthreads();
        gemm_qk<1>(Qs, Ks, Pb, rho, gg, 0, SCALE_MUL, q0);
        __syncthreads();
        load_tile_kv(Ks, k, b, h, j1 * 16, tid, false);
        __syncthreads();
        gemm_qk<1>(Qs, Ks, Pb, rho, gg, 64, SCALE_MUL, q0);
        __syncthreads();

        softmax_rows(Pb, rmax, rinv, red, 128, tid);
        scale_rows(Pb, rinv, gts, 1, 128, tid);

        load_tile_kv(Vs, v, b, h, j0 * 16, tid, false);
        __syncthreads();
        gemm_pv(Pb, Vs, acc, rho, gg, 0);
        __syncthreads();
        load_tile_kv(Vs, v, b, h, j1 * 16, tid, false);
        __syncthreads();
        gemm_pv(Pb, Vs, acc, rho, gg, 64);
        __syncthreads();
    }

    // ================= WINDOW branch =================
    {
        int wbase = q0 - WINR;
#pragma unroll 1
        for (int kt = 0; kt < 5; ++kt) {
            load_tile_kv(Ks, k, b, h, wbase + kt * 64, tid, true);
            __syncthreads();
            gemm_qk<2>(Qs, Ks, Pb, rho, gg, kt * 64, SCALE_MUL, q0);
            __syncthreads();
        }
        softmax_rows(Pb, rmax, rinv, red, 320, tid);
        scale_rows(Pb, rinv, gts, 2, 320, tid);
#pragma unroll 1
        for (int kt = 0; kt < 5; ++kt) {
            load_tile_kv(Vs, v, b, h, wbase + kt * 64, tid, true);
            __syncthreads();
            gemm_pv(Pb, Vs, acc, rho, gg, kt * 64);
            __syncthreads();
        }
    }

    // ---- write output ----
#pragma unroll
    for (int i = 0; i < 4; ++i) {
        int r = rho + 16 * i;
        float* op = out + ((size_t)(b * Sn + q0 + r) * Hn + h) * DIMn + gg;
#pragma unroll
        for (int j = 0; j < 8; ++j) op[16 * j] = acc[i][j];
    }
}

// ---------------- launch ----------------
extern "C" void kernel_launch(void* const* d_in, const int* in_sizes, int n_in,
                              void* d_out, int out_size)
{
    (void)in_sizes; (void)n_in; (void)out_size;
    const float* q   = (const float*)d_in[0];
    const float* k   = (const float*)d_in[1];
    const float* v   = (const float*)d_in[2];
    const float* wck = (const float*)d_in[3];
    const float* bck = (const float*)d_in[4];
    const float* wcv = (const float*)d_in[5];
    const float* bcv = (const float*)d_in[6];
    const float* wg  = (const float*)d_in[7];
    const float* bg  = (const float*)d_in[8];
    float* out = (float*)d_out;

    // kernel A: compressed K/V
    int totalA = Bn * Hn * NCMP * DIMn;
    cmp_kv_kernel<<<(totalA + 255) / 256, 256>>>(k, v, wck, bck, wcv, bcv);

    // fused NSA kernel
    size_t smem_floats = (size_t)3 * 64 * QSTR + (size_t)64 * PSTR
                       + 64 + 64 + 256 + 192 + 64 + 64 + 384 + 4;
    size_t smem_bytes = smem_floats * sizeof(float);
    cudaFuncSetAttribute(nsa_main, cudaFuncAttributeMaxDynamicSharedMemorySize,
                         (int)smem_bytes);
    nsa_main<<<Bn * Hn * NQB, 256, smem_bytes>>>(q, k, v, wg, bg, out);
}

// round 7
// speedup vs baseline: 1.1643x; 1.1643x over previous
#include <cuda_runtime.h>

// ---------------- problem constants ----------------
#define Bn    2
#define Sn    1024
#define Hn    8
#define DIMn  128
#define LCMP  32
#define NCMP  63          // (1024-32)/16+1
#define NSLC  61          // (1024-64)/16+1
#define BQ    64
#define NQB   (Sn / BQ)   // 16
#define WINR  128
#define QSTR  129         // padded row stride (conflict-free scalar LDS)
#define PSTR  133         // logit buffer row stride (>=128, odd vs 32 banks)
#define NEG_INF (-1e30f)

#define SCALE_MUL 0.08838834764831845f   // 1/sqrt(128): slc & window
#define SQRT_D    11.313708498984761f    // sqrt(128): cmp branch (reference divides by scale)

// scratch for compressed K/V: [b][h][n][d]
__device__ float g_cmpK[Bn * Hn * NCMP * DIMn];
__device__ float g_cmpV[Bn * Hn * NCMP * DIMn];

// ---------------- kernel A: compressed K/V ----------------
__global__ void __launch_bounds__(256) cmp_kv_kernel(
    const float* __restrict__ k, const float* __restrict__ v,
    const float* __restrict__ wck, const float* __restrict__ bck,
    const float* __restrict__ wcv, const float* __restrict__ bcv)
{
    __shared__ float swk[LCMP], swv[LCMP], sb[2];
    int tid = threadIdx.x;
    if (tid < LCMP) { swk[tid] = wck[tid]; swv[tid] = wcv[tid]; }
    if (tid == 0)   { sb[0] = bck[0]; sb[1] = bcv[0]; }
    __syncthreads();

    int idx = blockIdx.x * 256 + tid;
    if (idx >= Bn * Hn * NCMP * DIMn) return;
    int d  = idx & (DIMn - 1);
    int n  = (idx >> 7) % NCMP;
    int bh = idx / (NCMP * DIMn);
    int h  = bh & (Hn - 1);
    int b  = bh >> 3;

    const float* kb = k + ((size_t)(b * Sn + n * 16) * Hn + h) * DIMn + d;
    const float* vb = v + ((size_t)(b * Sn + n * 16) * Hn + h) * DIMn + d;
    float ak = 0.f, av = 0.f;
#pragma unroll
    for (int l = 0; l < LCMP; ++l) {
        ak += kb[(size_t)l * Hn * DIMn] * swk[l];
        av += vb[(size_t)l * Hn * DIMn] * swv[l];
    }
    g_cmpK[idx] = ak + sb[0];
    g_cmpV[idx] = av + sb[1];
}

// ---------------- helpers for the fused kernel ----------------

// QK core: s[4][4] = Qs(64x128) * Ks(64x128)^T register tile (no scale/mask)
__device__ __forceinline__ void qk_core(const float* __restrict__ Qs,
                                        const float* __restrict__ Ks,
                                        float s[4][4], int rho, int gg)
{
#pragma unroll
    for (int i = 0; i < 4; ++i)
#pragma unroll
        for (int j = 0; j < 4; ++j) s[i][j] = 0.f;

    const float* qp = Qs + rho * QSTR;
    const float* kp = Ks + gg  * QSTR;
#pragma unroll 4
    for (int kd = 0; kd < DIMn; ++kd) {
        float a0 = qp[kd];
        float a1 = qp[16 * QSTR + kd];
        float a2 = qp[32 * QSTR + kd];
        float a3 = qp[48 * QSTR + kd];
        float b0 = kp[kd];
        float b1 = kp[16 * QSTR + kd];
        float b2 = kp[32 * QSTR + kd];
        float b3 = kp[48 * QSTR + kd];
        s[0][0] += a0 * b0; s[0][1] += a0 * b1; s[0][2] += a0 * b2; s[0][3] += a0 * b3;
        s[1][0] += a1 * b0; s[1][1] += a1 * b1; s[1][2] += a1 * b2; s[1][3] += a1 * b3;
        s[2][0] += a2 * b0; s[2][1] += a2 * b1; s[2][2] += a2 * b2; s[2][3] += a2 * b3;
        s[3][0] += a3 * b0; s[3][1] += a3 * b1; s[3][2] += a3 * b2; s[3][3] += a3 * b3;
    }
}

// QK GEMM -> Pb.  MODE 0 = cmp (mask c>=NCMP), 1 = slc (no mask)
template <int MODE>
__device__ __forceinline__ void gemm_qk(const float* __restrict__ Qs,
                                        const float* __restrict__ Ks,
                                        float* __restrict__ Pb,
                                        int rho, int gg, int cb, float scl)
{
    float s[4][4];
    qk_core(Qs, Ks, s, rho, gg);
#pragma unroll
    for (int i = 0; i < 4; ++i) {
        int r = rho + 16 * i;
#pragma unroll
        for (int j = 0; j < 4; ++j) {
            int c = gg + 16 * j;
            float val = s[i][j] * scl;
            if (MODE == 0) {
                if (c >= NCMP) val = NEG_INF;
            }
            Pb[r * PSTR + cb + c] = val;
        }
    }
}

// PV GEMM: acc[4][8] += P(64 x 64-tile) * Vs(64x128)
__device__ __forceinline__ void gemm_pv(const float* __restrict__ Pb,
                                        const float* __restrict__ Vs,
                                        float acc[4][8], int rho, int gg, int cb)
{
    const float* pp = Pb + rho * PSTR + cb;
#pragma unroll 2
    for (int cl = 0; cl < 64; ++cl) {
        float p0 = pp[cl];
        float p1 = pp[16 * PSTR + cl];
        float p2 = pp[32 * PSTR + cl];
        float p3 = pp[48 * PSTR + cl];
        const float* vr = Vs + cl * QSTR + gg;
#pragma unroll
        for (int j = 0; j < 8; ++j) {
            float vv = vr[16 * j];
            acc[0][j] += p0 * vv;
            acc[1][j] += p1 * vv;
            acc[2][j] += p2 * vv;
            acc[3][j] += p3 * vv;
        }
    }
}

// two-pass row softmax over Pb[:, 0:NK]; leaves exp() in Pb, 1/rowsum in rinv
__device__ __forceinline__ void softmax_rows(float* __restrict__ Pb,
                                             float* __restrict__ rmax,
                                             float* __restrict__ rinv,
                                             float* __restrict__ red,
                                             int NK, int tid)
{
    int r = tid & 63, part = tid >> 6;
    float m = NEG_INF;
    for (int c = part; c < NK; c += 4) m = fmaxf(m, Pb[r * PSTR + c]);
    red[part * 64 + r] = m;
    __syncthreads();
    if (tid < 64)
        rmax[tid] = fmaxf(fmaxf(red[tid], red[64 + tid]),
                          fmaxf(red[128 + tid], red[192 + tid]));
    __syncthreads();
    float mr = rmax[r];
    float sum = 0.f;
    for (int c = part; c < NK; c += 4) {
        float e = __expf(Pb[r * PSTR + c] - mr);
        Pb[r * PSTR + c] = e;
        sum += e;
    }
    red[part * 64 + r] = sum;
    __syncthreads();
    if (tid < 64)
        rinv[tid] = 1.0f / (red[tid] + red[64 + tid] + red[128 + tid] + red[192 + tid]);
    __syncthreads();
}

// P[r][c] *= gate[r][gi] / rowsum[r]
__device__ __forceinline__ void scale_rows(float* __restrict__ Pb,
                                           const float* __restrict__ rinv,
                                           const float* __restrict__ gts,
                                           int gi, int NK, int tid)
{
    int r = tid & 63, part = tid >> 6;
    float f = gts[r * 3 + gi] * rinv[r];
    for (int c = part; c < NK; c += 4) Pb[r * PSTR + c] *= f;
    __syncthreads();
}

// load a 64x128 tile from q/k/v-layout global memory into padded smem, zero-fill invalid
__device__ __forceinline__ void load_tile_kv(float* __restrict__ dst,
                                             const float* __restrict__ src,
                                             int b, int h, int s_base, int tid, bool check)
{
    for (int idx = tid; idx < 64 * 32; idx += 256) {
        int t = idx >> 5, d4 = idx & 31;
        int srow = s_base + t;
        float4 val = make_float4(0.f, 0.f, 0.f, 0.f);
        if (!check || ((unsigned)srow < (unsigned)Sn))
            val = ((const float4*)(src + ((size_t)(b * Sn + srow) * Hn + h) * DIMn))[d4];
        float* ds = &dst[t * QSTR + (d4 << 2)];
        ds[0] = val.x; ds[1] = val.y; ds[2] = val.z; ds[3] = val.w;
    }
}

// load compressed K/V tile (63 rows), zero row 63
__device__ __forceinline__ void load_tile_cmp(float* __restrict__ dst,
                                              const float* __restrict__ src,
                                              int bh, int tid)
{
    for (int idx = tid; idx < 64 * 32; idx += 256) {
        int t = idx >> 5, d4 = idx & 31;
        float4 val = make_float4(0.f, 0.f, 0.f, 0.f);
        if (t < NCMP)
            val = ((const float4*)(src + ((size_t)bh * NCMP + t) * DIMn))[d4];
        float* ds = &dst[t * QSTR + (d4 << 2)];
        ds[0] = val.x; ds[1] = val.y; ds[2] = val.z; ds[3] = val.w;
    }
}

// ---------------- fused main kernel ----------------
__global__ void __launch_bounds__(256, 2) nsa_main(
    const float* __restrict__ q, const float* __restrict__ k, const float* __restrict__ v,
    const float* __restrict__ wgate, const float* __restrict__ bgate,
    float* __restrict__ out)
{
    extern __shared__ float sm[];
    float* Qs   = sm;                    // 64*129
    float* KV   = Qs  + 64 * QSTR;       // 64*129 (shared K/V tile)
    float* Pb   = KV  + 64 * QSTR;       // 64*133
    float* rinv = Pb  + 64 * PSTR;       // 64
    float* rmax = rinv + 64;             // 64
    float* red  = rmax + 64;             // 256
    float* gts  = red  + 256;            // 192
    float* Cs   = gts  + 192;            // 64
    float* Gb   = Cs   + 64;             // 64
    float* wgs  = Gb   + 64;             // 384
    int*   topi = (int*)(wgs + 384);     // 2

    const int tid = threadIdx.x;
    const int bhq = blockIdx.x;
    const int qb  = bhq & (NQB - 1);
    const int bh  = bhq >> 4;
    const int h   = bh & (Hn - 1);
    const int b   = bh >> 3;
    const int q0  = qb * BQ;
    const int rho = tid >> 4;   // 0..15 row group
    const int gg  = tid & 15;   // 0..15 col group

    // ---- load Q tile + gate weights ----
    {
        const float4* q4 = (const float4*)(q + ((size_t)(b * Sn + q0) * Hn + h) * DIMn);
        for (int idx = tid; idx < 64 * 32; idx += 256) {
            int t = idx >> 5, d4 = idx & 31;
            float4 val = q4[(size_t)t * (Hn * DIMn / 4) + d4];
            float* ds = &Qs[t * QSTR + (d4 << 2)];
            ds[0] = val.x; ds[1] = val.y; ds[2] = val.z; ds[3] = val.w;
        }
        for (int i = tid; i < 3 * DIMn; i += 256) wgs[i] = wgate[i];
    }
    __syncthreads();

    // ---- gates: sigmoid(q . w_gate[c] + b_gate[c]) ----
    if (tid < 192) {
        int r = tid / 3, c = tid - 3 * r;
        float a = bgate[c];
        const float* qr = &Qs[r * QSTR];
        const float* wr = &wgs[c * DIMn];
#pragma unroll 8
        for (int d = 0; d < DIMn; ++d) a += qr[d] * wr[d];
        gts[r * 3 + c] = 1.0f / (1.0f + __expf(-a));
    }
    __syncthreads();

    float acc[4][8];
#pragma unroll
    for (int i = 0; i < 4; ++i)
#pragma unroll
        for (int j = 0; j < 8; ++j) acc[i][j] = 0.f;

    // ================= WINDOW branch (flash-style online softmax) =================
    {
        const int wbase = q0 - WINR;
        float m_[4], l_[4];
#pragma unroll
        for (int i = 0; i < 4; ++i) { m_[i] = NEG_INF; l_[i] = 0.f; }

#pragma unroll 1
        for (int kt = 0; kt < 5; ++kt) {
            load_tile_kv(KV, k, b, h, wbase + kt * 64, tid, true);
            __syncthreads();

            float s[4][4];
            qk_core(Qs, KV, s, rho, gg);

            // scale + band/range mask
#pragma unroll
            for (int i = 0; i < 4; ++i) {
                int r = rho + 16 * i;
#pragma unroll
                for (int j = 0; j < 4; ++j) {
                    int cgl = kt * 64 + gg + 16 * j;
                    int key = wbase + cgl;
                    bool ok = (key >= 0) && (key < Sn) && (cgl >= r) && (cgl <= r + 2 * WINR);
                    s[i][j] = ok ? s[i][j] * SCALE_MUL : NEG_INF;
                }
            }

            // online softmax update; stats replicated over the 16-lane column group
#pragma unroll
            for (int i = 0; i < 4; ++i) {
                float tm = fmaxf(fmaxf(s[i][0], s[i][1]), fmaxf(s[i][2], s[i][3]));
                tm = fmaxf(tm, __shfl_xor_sync(0xffffffffu, tm, 1));
                tm = fmaxf(tm, __shfl_xor_sync(0xffffffffu, tm, 2));
                tm = fmaxf(tm, __shfl_xor_sync(0xffffffffu, tm, 4));
                tm = fmaxf(tm, __shfl_xor_sync(0xffffffffu, tm, 8));
                float nm = fmaxf(m_[i], tm);
                float sc = __expf(m_[i] - nm);   // ==1 when both -inf (acc is 0 there)
                m_[i] = nm;
                float rs = 0.f;
#pragma unroll
                for (int j = 0; j < 4; ++j) {
                    float e = (s[i][j] > -1e29f) ? __expf(s[i][j] - nm) : 0.f;
                    s[i][j] = e;
                    rs += e;
                }
                rs += __shfl_xor_sync(0xffffffffu, rs, 1);
                rs += __shfl_xor_sync(0xffffffffu, rs, 2);
                rs += __shfl_xor_sync(0xffffffffu, rs, 4);
                rs += __shfl_xor_sync(0xffffffffu, rs, 8);
                l_[i] = l_[i] * sc + rs;
#pragma unroll
                for (int j = 0; j < 8; ++j) acc[i][j] *= sc;
                int r = rho + 16 * i;
#pragma unroll
                for (int j = 0; j < 4; ++j) Pb[r * PSTR + gg + 16 * j] = s[i][j];
            }
            __syncthreads();  // Pb written, K reads done

            load_tile_kv(KV, v, b, h, wbase + kt * 64, tid, true);
            __syncthreads();
            gemm_pv(Pb, KV, acc, rho, gg, 0);
            __syncthreads();
        }
        // finalize window: acc *= gate2 / rowsum
#pragma unroll
        for (int i = 0; i < 4; ++i) {
            int r = rho + 16 * i;
            float f = gts[r * 3 + 2] / l_[i];
#pragma unroll
            for (int j = 0; j < 8; ++j) acc[i][j] *= f;
        }
    }

    // ================= CMP branch =================
    load_tile_cmp(KV, g_cmpK, bh, tid);
    __syncthreads();
    gemm_qk<0>(Qs, KV, Pb, rho, gg, 0, SQRT_D);
    __syncthreads();
    softmax_rows(Pb, rmax, rinv, red, 64, tid);

    // column sums of normalized P_cmp
    if (tid < NCMP) {
        float s = 0.f;
#pragma unroll 4
        for (int r = 0; r < 64; ++r) s += Pb[r * PSTR + tid] * rinv[r];
        Cs[tid] = s;
    }
    __syncthreads();
    // slc-map convolution: weights 1,2,2,2,1 at i = 4j, 4j-1, 4j-2, 4j-3, 4j-4
    if (tid < NSLC) {
        int j4 = 4 * tid;
        float g = 0.f;
        if (j4 < NCMP)                       g += Cs[j4];
        if (j4 - 1 >= 0 && j4 - 1 < NCMP)    g += 2.f * Cs[j4 - 1];
        if (j4 - 2 >= 0 && j4 - 2 < NCMP)    g += 2.f * Cs[j4 - 2];
        if (j4 - 3 >= 0 && j4 - 3 < NCMP)    g += 2.f * Cs[j4 - 3];
        if (j4 - 4 >= 0 && j4 - 4 < NCMP)    g += Cs[j4 - 4];
        Gb[tid] = g;
    }
    __syncthreads();
    // deterministic top-2 (jax tie rule: lower index first)
    if (tid == 0) {
        int i0 = 0; float v0 = Gb[0];
        for (int j = 1; j < NSLC; ++j) if (Gb[j] > v0) { v0 = Gb[j]; i0 = j; }
        int i1 = 0; float v1 = NEG_INF;
        for (int j = 0; j < NSLC; ++j) if (j != i0 && Gb[j] > v1) { v1 = Gb[j]; i1 = j; }
        topi[0] = i0; topi[1] = i1;
    }
    scale_rows(Pb, rinv, gts, 0, 64, tid);   // fold in gate0 (ends with sync -> topi visible)
    load_tile_cmp(KV, g_cmpV, bh, tid);
    __syncthreads();
    gemm_pv(Pb, KV, acc, rho, gg, 0);
    __syncthreads();

    // ================= SLC branch =================
    {
        int j0 = topi[0], j1 = topi[1];
        load_tile_kv(KV, k, b, h, j0 * 16, tid, false);
        __syncthreads();
        gemm_qk<1>(Qs, KV, Pb, rho, gg, 0, SCALE_MUL);
        __syncthreads();
        load_tile_kv(KV, k, b, h, j1 * 16, tid, false);
        __syncthreads();
        gemm_qk<1>(Qs, KV, Pb, rho, gg, 64, SCALE_MUL);
        __syncthreads();

        softmax_rows(Pb, rmax, rinv, red, 128, tid);
        scale_rows(Pb, rinv, gts, 1, 128, tid);

        load_tile_kv(KV, v, b, h, j0 * 16, tid, false);
        __syncthreads();
        gemm_pv(Pb, KV, acc, rho, gg, 0);
        __syncthreads();
        load_tile_kv(KV, v, b, h, j1 * 16, tid, false);
        __syncthreads();
        gemm_pv(Pb, KV, acc, rho, gg, 64);
    }

    // ---- write output ----
#pragma unroll
    for (int i = 0; i < 4; ++i) {
        int r = rho + 16 * i;
        float* op = out + ((size_t)(b * Sn + q0 + r) * Hn + h) * DIMn + gg;
#pragma unroll
        for (int j = 0; j < 8; ++j) op[16 * j] = acc[i][j];
    }
}

// ---------------- launch ----------------
extern "C" void kernel_launch(void* const* d_in, const int* in_sizes, int n_in,
                              void* d_out, int out_size)
{
    (void)in_sizes; (void)n_in; (void)out_size;
    const float* q   = (const float*)d_in[0];
    const float* k   = (const float*)d_in[1];
    const float* v   = (const float*)d_in[2];
    const float* wck = (const float*)d_in[3];
    const float* bck = (const float*)d_in[4];
    const float* wcv = (const float*)d_in[5];
    const float* bcv = (const float*)d_in[6];
    const float* wg  = (const float*)d_in[7];
    const float* bg  = (const float*)d_in[8];
    float* out = (float*)d_out;

    // kernel A: compressed K/V
    int totalA = Bn * Hn * NCMP * DIMn;
    cmp_kv_kernel<<<(totalA + 255) / 256, 256>>>(k, v, wck, bck, wcv, bcv);

    // fused NSA kernel
    size_t smem_floats = (size_t)2 * 64 * QSTR + (size_t)64 * PSTR
                       + 64 + 64 + 256 + 192 + 64 + 64 + 384 + 4;
    size_t smem_bytes = smem_floats * sizeof(float);
    cudaFuncSetAttribute(nsa_main, cudaFuncAttributeMaxDynamicSharedMemorySize,
                         (int)smem_bytes);
    nsa_main<<<Bn * Hn * NQB, 256, smem_bytes>>>(q, k, v, wg, bg, out);
}

// round 8
// speedup vs baseline: 1.1659x; 1.0014x over previous
#include <cuda_runtime.h>

// ---------------- problem constants ----------------
#define Bn    2
#define Sn    1024
#define Hn    8
#define DIMn  128
#define LCMP  32
#define NCMP  63          // (1024-32)/16+1
#define NSLC  61          // (1024-64)/16+1
#define BQ    64
#define NQB   (Sn / BQ)   // 16
#define WINR  128
#define QSTR  129         // padded row stride (conflict-free scalar LDS)
#define PSTR  133         // logit buffer row stride (>=128, odd vs 32 banks)
#define NEG_INF (-1e30f)

#define SCALE_MUL 0.08838834764831845f   // 1/sqrt(128): slc & window
#define SQRT_D    11.313708498984761f    // sqrt(128): cmp branch (reference divides by scale)

// scratch for compressed K/V: [b][h][n][d]
__device__ float g_cmpK[Bn * Hn * NCMP * DIMn];
__device__ float g_cmpV[Bn * Hn * NCMP * DIMn];

// ---------------- kernel A: compressed K/V ----------------
__global__ void __launch_bounds__(256) cmp_kv_kernel(
    const float* __restrict__ k, const float* __restrict__ v,
    const float* __restrict__ wck, const float* __restrict__ bck,
    const float* __restrict__ wcv, const float* __restrict__ bcv)
{
    __shared__ float swk[LCMP], swv[LCMP], sb[2];
    int tid = threadIdx.x;
    if (tid < LCMP) { swk[tid] = wck[tid]; swv[tid] = wcv[tid]; }
    if (tid == 0)   { sb[0] = bck[0]; sb[1] = bcv[0]; }
    __syncthreads();

    int idx = blockIdx.x * 256 + tid;
    if (idx >= Bn * Hn * NCMP * DIMn) return;
    int d  = idx & (DIMn - 1);
    int n  = (idx >> 7) % NCMP;
    int bh = idx / (NCMP * DIMn);
    int h  = bh & (Hn - 1);
    int b  = bh >> 3;

    const float* kb = k + ((size_t)(b * Sn + n * 16) * Hn + h) * DIMn + d;
    const float* vb = v + ((size_t)(b * Sn + n * 16) * Hn + h) * DIMn + d;
    float ak = 0.f, av = 0.f;
#pragma unroll
    for (int l = 0; l < LCMP; ++l) {
        ak += kb[(size_t)l * Hn * DIMn] * swk[l];
        av += vb[(size_t)l * Hn * DIMn] * swv[l];
    }
    g_cmpK[idx] = ak + sb[0];
    g_cmpV[idx] = av + sb[1];
}

// ---------------- helpers for the fused kernel ----------------

// QK core: s[4][4] = Qs(64x128) * Ks(64x128)^T register tile (no scale/mask)
__device__ __forceinline__ void qk_core(const float* __restrict__ Qs,
                                        const float* __restrict__ Ks,
                                        float s[4][4], int rho, int gg)
{
#pragma unroll
    for (int i = 0; i < 4; ++i)
#pragma unroll
        for (int j = 0; j < 4; ++j) s[i][j] = 0.f;

    const float* qp = Qs + rho * QSTR;
    const float* kp = Ks + gg  * QSTR;
#pragma unroll 4
    for (int kd = 0; kd < DIMn; ++kd) {
        float a0 = qp[kd];
        float a1 = qp[16 * QSTR + kd];
        float a2 = qp[32 * QSTR + kd];
        float a3 = qp[48 * QSTR + kd];
        float b0 = kp[kd];
        float b1 = kp[16 * QSTR + kd];
        float b2 = kp[32 * QSTR + kd];
        float b3 = kp[48 * QSTR + kd];
        s[0][0] += a0 * b0; s[0][1] += a0 * b1; s[0][2] += a0 * b2; s[0][3] += a0 * b3;
        s[1][0] += a1 * b0; s[1][1] += a1 * b1; s[1][2] += a1 * b2; s[1][3] += a1 * b3;
        s[2][0] += a2 * b0; s[2][1] += a2 * b1; s[2][2] += a2 * b2; s[2][3] += a2 * b3;
        s[3][0] += a3 * b0; s[3][1] += a3 * b1; s[3][2] += a3 * b2; s[3][3] += a3 * b3;
    }
}

// QK GEMM -> Pb.  MODE 0 = cmp (mask c>=NCMP), 1 = slc (no mask)
template <int MODE>
__device__ __forceinline__ void gemm_qk(const float* __restrict__ Qs,
                                        const float* __restrict__ Ks,
                                        float* __restrict__ Pb,
                                        int rho, int gg, int cb, float scl)
{
    float s[4][4];
    qk_core(Qs, Ks, s, rho, gg);
#pragma unroll
    for (int i = 0; i < 4; ++i) {
        int r = rho + 16 * i;
#pragma unroll
        for (int j = 0; j < 4; ++j) {
            int c = gg + 16 * j;
            float val = s[i][j] * scl;
            if (MODE == 0) {
                if (c >= NCMP) val = NEG_INF;
            }
            Pb[r * PSTR + cb + c] = val;
        }
    }
}

// PV GEMM: acc[4][8] += P(64 x 64-tile) * Vs(64x128)
__device__ __forceinline__ void gemm_pv(const float* __restrict__ Pb,
                                        const float* __restrict__ Vs,
                                        float acc[4][8], int rho, int gg, int cb)
{
    const float* pp = Pb + rho * PSTR + cb;
#pragma unroll 2
    for (int cl = 0; cl < 64; ++cl) {
        float p0 = pp[cl];
        float p1 = pp[16 * PSTR + cl];
        float p2 = pp[32 * PSTR + cl];
        float p3 = pp[48 * PSTR + cl];
        const float* vr = Vs + cl * QSTR + gg;
#pragma unroll
        for (int j = 0; j < 8; ++j) {
            float vv = vr[16 * j];
            acc[0][j] += p0 * vv;
            acc[1][j] += p1 * vv;
            acc[2][j] += p2 * vv;
            acc[3][j] += p3 * vv;
        }
    }
}

// two-pass row softmax over Pb[:, 0:NK]; leaves exp() in Pb, 1/rowsum in rinv
__device__ __forceinline__ void softmax_rows(float* __restrict__ Pb,
                                             float* __restrict__ rmax,
                                             float* __restrict__ rinv,
                                             float* __restrict__ red,
                                             int NK, int tid)
{
    int r = tid & 63, part = tid >> 6;
    float m = NEG_INF;
    for (int c = part; c < NK; c += 4) m = fmaxf(m, Pb[r * PSTR + c]);
    red[part * 64 + r] = m;
    __syncthreads();
    if (tid < 64)
        rmax[tid] = fmaxf(fmaxf(red[tid], red[64 + tid]),
                          fmaxf(red[128 + tid], red[192 + tid]));
    __syncthreads();
    float mr = rmax[r];
    float sum = 0.f;
    for (int c = part; c < NK; c += 4) {
        float e = __expf(Pb[r * PSTR + c] - mr);
        Pb[r * PSTR + c] = e;
        sum += e;
    }
    red[part * 64 + r] = sum;
    __syncthreads();
    if (tid < 64)
        rinv[tid] = 1.0f / (red[tid] + red[64 + tid] + red[128 + tid] + red[192 + tid]);
    __syncthreads();
}

// P[r][c] *= gate[r][gi] / rowsum[r]
__device__ __forceinline__ void scale_rows(float* __restrict__ Pb,
                                           const float* __restrict__ rinv,
                                           const float* __restrict__ gts,
                                           int gi, int NK, int tid)
{
    int r = tid & 63, part = tid >> 6;
    float f = gts[r * 3 + gi] * rinv[r];
    for (int c = part; c < NK; c += 4) Pb[r * PSTR + c] *= f;
    __syncthreads();
}

// load a 64x128 tile from q/k/v-layout global memory into padded smem, zero-fill invalid
__device__ __forceinline__ void load_tile_kv(float* __restrict__ dst,
                                             const float* __restrict__ src,
                                             int b, int h, int s_base, int tid, bool check)
{
    for (int idx = tid; idx < 64 * 32; idx += 256) {
        int t = idx >> 5, d4 = idx & 31;
        int srow = s_base + t;
        float4 val = make_float4(0.f, 0.f, 0.f, 0.f);
        if (!check || ((unsigned)srow < (unsigned)Sn))
            val = ((const float4*)(src + ((size_t)(b * Sn + srow) * Hn + h) * DIMn))[d4];
        float* ds = &dst[t * QSTR + (d4 << 2)];
        ds[0] = val.x; ds[1] = val.y; ds[2] = val.z; ds[3] = val.w;
    }
}

// load compressed K/V tile (63 rows), zero row 63
__device__ __forceinline__ void load_tile_cmp(float* __restrict__ dst,
                                              const float* __restrict__ src,
                                              int bh, int tid)
{
    for (int idx = tid; idx < 64 * 32; idx += 256) {
        int t = idx >> 5, d4 = idx & 31;
        float4 val = make_float4(0.f, 0.f, 0.f, 0.f);
        if (t < NCMP)
            val = ((const float4*)(src + ((size_t)bh * NCMP + t) * DIMn))[d4];
        float* ds = &dst[t * QSTR + (d4 << 2)];
        ds[0] = val.x; ds[1] = val.y; ds[2] = val.z; ds[3] = val.w;
    }
}

// ---------------- fused main kernel ----------------
__global__ void __launch_bounds__(256, 2) nsa_main(
    const float* __restrict__ q, const float* __restrict__ k, const float* __restrict__ v,
    const float* __restrict__ wgate, const float* __restrict__ bgate,
    float* __restrict__ out)
{
    extern __shared__ float sm[];
    float* Qs   = sm;                    // 64*129
    float* KV   = Qs  + 64 * QSTR;       // 64*129 (shared K/V tile)
    float* Pb   = KV  + 64 * QSTR;       // 64*133
    float* rinv = Pb  + 64 * PSTR;       // 64
    float* rmax = rinv + 64;             // 64
    float* red  = rmax + 64;             // 256
    float* gts  = red  + 256;            // 192
    float* Cs   = gts  + 192;            // 64
    float* Gb   = Cs   + 64;             // 64
    float* wgs  = Gb   + 64;             // 384
    int*   topi = (int*)(wgs + 384);     // 2

    const int tid = threadIdx.x;
    const int bhq = blockIdx.x;
    const int qb  = bhq & (NQB - 1);
    const int bh  = bhq >> 4;
    const int h   = bh & (Hn - 1);
    const int b   = bh >> 3;
    const int q0  = qb * BQ;
    const int rho = tid >> 4;   // 0..15 row group
    const int gg  = tid & 15;   // 0..15 col group

    // ---- load Q tile + gate weights ----
    {
        const float4* q4 = (const float4*)(q + ((size_t)(b * Sn + q0) * Hn + h) * DIMn);
        for (int idx = tid; idx < 64 * 32; idx += 256) {
            int t = idx >> 5, d4 = idx & 31;
            float4 val = q4[(size_t)t * (Hn * DIMn / 4) + d4];
            float* ds = &Qs[t * QSTR + (d4 << 2)];
            ds[0] = val.x; ds[1] = val.y; ds[2] = val.z; ds[3] = val.w;
        }
        for (int i = tid; i < 3 * DIMn; i += 256) wgs[i] = wgate[i];
    }
    __syncthreads();

    // ---- gates: sigmoid(q . w_gate[c] + b_gate[c]) ----
    if (tid < 192) {
        int r = tid / 3, c = tid - 3 * r;
        float a = bgate[c];
        const float* qr = &Qs[r * QSTR];
        const float* wr = &wgs[c * DIMn];
#pragma unroll 8
        for (int d = 0; d < DIMn; ++d) a += qr[d] * wr[d];
        gts[r * 3 + c] = 1.0f / (1.0f + __expf(-a));
    }
    __syncthreads();

    float acc[4][8];
#pragma unroll
    for (int i = 0; i < 4; ++i)
#pragma unroll
        for (int j = 0; j < 8; ++j) acc[i][j] = 0.f;

    // ================= WINDOW branch (flash-style online softmax) =================
    {
        const int wbase = q0 - WINR;
        float m_[4], l_[4];
#pragma unroll
        for (int i = 0; i < 4; ++i) { m_[i] = NEG_INF; l_[i] = 0.f; }

#pragma unroll 1
        for (int kt = 0; kt < 5; ++kt) {
            load_tile_kv(KV, k, b, h, wbase + kt * 64, tid, true);
            __syncthreads();

            float s[4][4];
            qk_core(Qs, KV, s, rho, gg);

            // scale + band/range mask
#pragma unroll
            for (int i = 0; i < 4; ++i) {
                int r = rho + 16 * i;
#pragma unroll
                for (int j = 0; j < 4; ++j) {
                    int cgl = kt * 64 + gg + 16 * j;
                    int key = wbase + cgl;
                    bool ok = (key >= 0) && (key < Sn) && (cgl >= r) && (cgl <= r + 2 * WINR);
                    s[i][j] = ok ? s[i][j] * SCALE_MUL : NEG_INF;
                }
            }

            // online softmax update; stats replicated over the 16-lane column group
#pragma unroll
            for (int i = 0; i < 4; ++i) {
                float tm = fmaxf(fmaxf(s[i][0], s[i][1]), fmaxf(s[i][2], s[i][3]));
                tm = fmaxf(tm, __shfl_xor_sync(0xffffffffu, tm, 1));
                tm = fmaxf(tm, __shfl_xor_sync(0xffffffffu, tm, 2));
                tm = fmaxf(tm, __shfl_xor_sync(0xffffffffu, tm, 4));
                tm = fmaxf(tm, __shfl_xor_sync(0xffffffffu, tm, 8));
                float nm = fmaxf(m_[i], tm);
                float sc = __expf(m_[i] - nm);   // ==1 when both -inf (acc is 0 there)
                m_[i] = nm;
                float rs = 0.f;
#pragma unroll
                for (int j = 0; j < 4; ++j) {
                    float e = (s[i][j] > -1e29f) ? __expf(s[i][j] - nm) : 0.f;
                    s[i][j] = e;
                    rs += e;
                }
                rs += __shfl_xor_sync(0xffffffffu, rs, 1);
                rs += __shfl_xor_sync(0xffffffffu, rs, 2);
                rs += __shfl_xor_sync(0xffffffffu, rs, 4);
                rs += __shfl_xor_sync(0xffffffffu, rs, 8);
                l_[i] = l_[i] * sc + rs;
#pragma unroll
                for (int j = 0; j < 8; ++j) acc[i][j] *= sc;
                int r = rho + 16 * i;
#pragma unroll
                for (int j = 0; j < 4; ++j) Pb[r * PSTR + gg + 16 * j] = s[i][j];
            }
            __syncthreads();  // Pb written, K reads done

            load_tile_kv(KV, v, b, h, wbase + kt * 64, tid, true);
            __syncthreads();
            gemm_pv(Pb, KV, acc, rho, gg, 0);
            __syncthreads();
        }
        // finalize window: acc *= gate2 / rowsum
#pragma unroll
        for (int i = 0; i < 4; ++i) {
            int r = rho + 16 * i;
            float f = gts[r * 3 + 2] / l_[i];
#pragma unroll
            for (int j = 0; j < 8; ++j) acc[i][j] *= f;
        }
    }

    // ================= CMP branch =================
    load_tile_cmp(KV, g_cmpK, bh, tid);
    __syncthreads();
    gemm_qk<0>(Qs, KV, Pb, rho, gg, 0, SQRT_D);
    __syncthreads();
    softmax_rows(Pb, rmax, rinv, red, 64, tid);

    // column sums of normalized P_cmp
    if (tid < NCMP) {
        float s = 0.f;
#pragma unroll 4
        for (int r = 0; r < 64; ++r) s += Pb[r * PSTR + tid] * rinv[r];
        Cs[tid] = s;
    }
    __syncthreads();
    // slc-map convolution: weights 1,2,2,2,1 at i = 4j, 4j-1, 4j-2, 4j-3, 4j-4
    if (tid < NSLC) {
        int j4 = 4 * tid;
        float g = 0.f;
        if (j4 < NCMP)                       g += Cs[j4];
        if (j4 - 1 >= 0 && j4 - 1 < NCMP)    g += 2.f * Cs[j4 - 1];
        if (j4 - 2 >= 0 && j4 - 2 < NCMP)    g += 2.f * Cs[j4 - 2];
        if (j4 - 3 >= 0 && j4 - 3 < NCMP)    g += 2.f * Cs[j4 - 3];
        if (j4 - 4 >= 0 && j4 - 4 < NCMP)    g += Cs[j4 - 4];
        Gb[tid] = g;
    }
    __syncthreads();
    // deterministic top-2 (jax tie rule: lower index first)
    if (tid == 0) {
        int i0 = 0; float v0 = Gb[0];
        for (int j = 1; j < NSLC; ++j) if (Gb[j] > v0) { v0 = Gb[j]; i0 = j; }
        int i1 = 0; float v1 = NEG_INF;
        for (int j = 0; j < NSLC; ++j) if (j != i0 && Gb[j] > v1) { v1 = Gb[j]; i1 = j; }
        topi[0] = i0; topi[1] = i1;
    }
    scale_rows(Pb, rinv, gts, 0, 64, tid);   // fold in gate0 (ends with sync -> topi visible)
    load_tile_cmp(KV, g_cmpV, bh, tid);
    __syncthreads();
    gemm_pv(Pb, KV, acc, rho, gg, 0);
    __syncthreads();

    // ================= SLC branch =================
    {
        int j0 = topi[0], j1 = topi[1];
        load_tile_kv(KV, k, b, h, j0 * 16, tid, false);
        __syncthreads();
        gemm_qk<1>(Qs, KV, Pb, rho, gg, 0, SCALE_MUL);
        __syncthreads();
        load_tile_kv(KV, k, b, h, j1 * 16, tid, false);
        __syncthreads();
        gemm_qk<1>(Qs, KV, Pb, rho, gg, 64, SCALE_MUL);
        __syncthreads();

        softmax_rows(Pb, rmax, rinv, red, 128, tid);
        scale_rows(Pb, rinv, gts, 1, 128, tid);

        load_tile_kv(KV, v, b, h, j0 * 16, tid, false);
        __syncthreads();
        gemm_pv(Pb, KV, acc, rho, gg, 0);
        __syncthreads();
        load_tile_kv(KV, v, b, h, j1 * 16, tid, false);
        __syncthreads();
        gemm_pv(Pb, KV, acc, rho, gg, 64);
    }

    // ---- write output ----
#pragma unroll
    for (int i = 0; i < 4; ++i) {
        int r = rho + 16 * i;
        float* op = out + ((size_t)(b * Sn + q0 + r) * Hn + h) * DIMn + gg;
#pragma unroll
        for (int j = 0; j < 8; ++j) op[16 * j] = acc[i][j];
    }
}

// ---------------- launch ----------------
extern "C" void kernel_launch(void* const* d_in, const int* in_sizes, int n_in,
                              void* d_out, int out_size)
{
    (void)in_sizes; (void)n_in; (void)out_size;
    const float* q   = (const float*)d_in[0];
    const float* k   = (const float*)d_in[1];
    const float* v   = (const float*)d_in[2];
    const float* wck = (const float*)d_in[3];
    const float* bck = (const float*)d_in[4];
    const float* wcv = (const float*)d_in[5];
    const float* bcv = (const float*)d_in[6];
    const float* wg  = (const float*)d_in[7];
    const float* bg  = (const float*)d_in[8];
    float* out = (float*)d_out;

    // kernel A: compressed K/V
    int totalA = Bn * Hn * NCMP * DIMn;
    cmp_kv_kernel<<<(totalA + 255) / 256, 256>>>(k, v, wck, bck, wcv, bcv);

    // fused NSA kernel
    size_t smem_floats = (size_t)2 * 64 * QSTR + (size_t)64 * PSTR
                       + 64 + 64 + 256 + 192 + 64 + 64 + 384 + 4;
    size_t smem_bytes = smem_floats * sizeof(float);
    cudaFuncSetAttribute(nsa_main, cudaFuncAttributeMaxDynamicSharedMemorySize,
                         (int)smem_bytes);
    nsa_main<<<Bn * Hn * NQB, 256, smem_bytes>>>(q, k, v, wg, bg, out);
}